// round 13
// baseline (speedup 1.0000x reference)
#include <cuda_runtime.h>
#include <cstdint>

#define LN_EPS 1e-5f
#define H 768
#define F 11
#define RPB 64            // rows per block
#define TPB 128           // 128 threads x 6 cols = 768 ; 4 warps -> all SMSPs
#define COLS 6
#define NPK 3             // f32x2 packs per thread (6 cols)
#define CHUNK 4           // rows per bulk-store chunk (12KB)
#define NBUF 4            // tile buffers (deep pipeline)
#define NCHUNK (RPB / CHUNK)
#define ROWBYTES (H * 4)  // 3072
#define FSTRIDE 28        // floats per fst row (13 dup pairs + 2 pad)

// [0..120] G[i*11+j], [121..131] ws, [132..142] Wb, [143] sum_b, [144] sum_b2
__device__ float g_stats[145];

typedef unsigned long long ull;

__device__ __forceinline__ ull fma2(ull a, ull b, ull c) {
    ull d; asm("fma.rn.f32x2 %0, %1, %2, %3;" : "=l"(d) : "l"(a), "l"(b), "l"(c)); return d;
}
__device__ __forceinline__ void unpk(ull v, float& lo, float& hi) {
    asm("mov.b64 {%0, %1}, %2;" : "=f"(lo), "=f"(hi) : "l"(v));
}
__device__ __forceinline__ ull pk2(float lo, float hi) {
    ull d; asm("mov.b64 %0, {%1, %2};" : "=l"(d) : "f"(lo), "f"(hi)); return d;
}
__device__ __forceinline__ uint32_t smem_u32(const void* p) {
    uint32_t a;
    asm("{ .reg .u64 t; cvta.to.shared.u64 t, %1; cvt.u32.u64 %0, t; }" : "=r"(a) : "l"(p));
    return a;
}

// ---------------------------------------------------------------------------
// Kernel A: weight statistics (145 tiny reductions over H=768)
// ---------------------------------------------------------------------------
__global__ void stats_kernel(const float* __restrict__ W, const float* __restrict__ b) {
    __shared__ float wsum[8];
    int blk = blockIdx.x, tid = threadIdx.x;
    float local = 0.f;
    if (blk < 121) {
        int i = blk / 11, j = blk % 11;
        for (int h = tid; h < H; h += 256) local += W[i * H + h] * W[j * H + h];
    } else if (blk < 132) {
        int f = blk - 121;
        for (int h = tid; h < H; h += 256) local += W[f * H + h];
    } else if (blk < 143) {
        int f = blk - 132;
        for (int h = tid; h < H; h += 256) local += W[f * H + h] * b[h];
    } else if (blk == 143) {
        for (int h = tid; h < H; h += 256) local += b[h];
    } else {
        for (int h = tid; h < H; h += 256) local += b[h] * b[h];
    }
    #pragma unroll
    for (int o = 16; o; o >>= 1) local += __shfl_xor_sync(0xffffffffu, local, o);
    if ((tid & 31) == 0) wsum[tid >> 5] = local;
    __syncthreads();
    if (tid == 0) {
        float s = 0.f;
        #pragma unroll
        for (int w = 0; w < 8; w++) s += wsum[w];
        g_stats[blk] = s;
    }
}

// ---------------------------------------------------------------------------
// Row compute core: one row's GEMV+LN+ReLU into smem tile (6 cols/thread)
// ---------------------------------------------------------------------------
struct ColCtx {
    ull gp[NPK], ep[NPK], bg[NPK];
    ull wg[F][NPK];
};

__device__ __forceinline__ void compute_row(const float* __restrict__ fsrow,
                                            const ColCtx& C, float* __restrict__ dst,
                                            int h0) {
    const ulonglong2* fq = (const ulonglong2*)fsrow;
    ulonglong2 q0 = fq[0], q1 = fq[1], q2 = fq[2];
    ulonglong2 q3 = fq[3], q4 = fq[4], q5 = fq[5];
    ull last = *(const ull*)(fsrow + 24);
    ull u[F] = {q0.x, q0.y, q1.x, q1.y, q2.x, q2.y,
                q3.x, q3.y, q4.x, q4.y, q5.x};
    ull s2 = q5.y;   // (inv, inv)
    ull p2 = last;   // (-mean*inv, -mean*inv)

    ull acc[NPK];
    #pragma unroll
    for (int k = 0; k < NPK; k++) acc[k] = fma2(p2, C.gp[k], C.ep[k]);
    #pragma unroll
    for (int k = 0; k < NPK; k++) acc[k] = fma2(s2, C.bg[k], acc[k]);
    #pragma unroll
    for (int f = 0; f < F; f++) {
        #pragma unroll
        for (int k = 0; k < NPK; k++) acc[k] = fma2(u[f], C.wg[f][k], acc[k]);
    }

    float v0, v1, v2, v3, v4, v5;
    unpk(acc[0], v0, v1); unpk(acc[1], v2, v3); unpk(acc[2], v4, v5);
    float2* op = (float2*)(dst + h0);
    op[0] = make_float2(fmaxf(v0, 0.f), fmaxf(v1, 0.f));
    op[1] = make_float2(fmaxf(v2, 0.f), fmaxf(v3, 0.f));
    op[2] = make_float2(fmaxf(v4, 0.f), fmaxf(v5, 0.f));
}

// ---------------------------------------------------------------------------
// Kernel B (fused): feats -> smem dup pairs, packed-FFMA2 GEMV+LN+ReLU into
// 4-deep buffered smem tiles, TMA bulk stores.
// ---------------------------------------------------------------------------
__global__ void __launch_bounds__(TPB, 3)
fused_kernel(const float* __restrict__ target, const float* __restrict__ boxes,
             const float* __restrict__ W, const float* __restrict__ b,
             const float* __restrict__ gamma, const float* __restrict__ beta,
             float* __restrict__ out, int N) {
    __shared__ __align__(128) float obuf[NBUF][CHUNK * H];   // 4 x 12KB
    __shared__ __align__(16)  float fst[RPB][FSTRIDE];       // 7KB
    float* st = obuf[0];   // stats staging aliases tile buffer (pre-loop only)

    int tid = threadIdx.x;
    int h0 = tid * COLS;

    for (int i = tid; i < 145; i += TPB) st[i] = g_stats[i];

    // resident slices (packed pairs): wg = W*gamma, bg = b*gamma, gp, ep
    ColCtx C;
    float g6[COLS];
    {
        const float2* g2 = (const float2*)(gamma + h0);
        const float2* e2 = (const float2*)(beta + h0);
        const float2* b2 = (const float2*)(b + h0);
        #pragma unroll
        for (int k = 0; k < NPK; k++) {
            float2 g = g2[k], e = e2[k], bb = b2[k];
            g6[2*k] = g.x; g6[2*k+1] = g.y;
            C.gp[k] = pk2(g.x, g.y);
            C.ep[k] = pk2(e.x, e.y);
            C.bg[k] = pk2(bb.x * g.x, bb.y * g.y);
        }
    }
    #pragma unroll
    for (int f = 0; f < F; f++) {
        const float2* w2 = (const float2*)(W + f * H + h0);
        #pragma unroll
        for (int k = 0; k < NPK; k++) {
            float2 wv = w2[k];
            C.wg[f][k] = pk2(wv.x * g6[2*k], wv.y * g6[2*k+1]);
        }
    }

    int r0blk = blockIdx.x * RPB;
    __syncthreads();   // st[] ready

    // ---- feats phase: one row per thread (tid < 64) ----
    if (tid < RPB) {
        int row = r0blk + tid;
        if (row < N) {
            float tx0 = target[0], ty0 = target[1], tx1 = target[2], ty1 = target[3];
            float4 bx = ((const float4*)boxes)[row];
            float x0 = bx.x, y0 = bx.y, x1 = bx.z, y1 = bx.w;

            float w1 = tx1 - tx0, h1 = ty1 - ty0;
            float w2 = x1 - x0,   h2 = y1 - y0;

            float t[F];
            t[0] = w1; t[1] = h1; t[2] = w2; t[3] = h2;
            t[4] = fabsf(w1 - w2); t[5] = fabsf(h1 - h2);

            float c1x = (tx0 + tx1) * 0.5f, c1y = (ty0 + ty1) * 0.5f;
            float c2x = (x0 + x1) * 0.5f,   c2y = (y0 + y1) * 0.5f;
            float dx = c2x - c1x, dy = c2y - c1y;
            t[6] = sqrtf(dx * dx + dy * dy);

            bool overlap = (tx0 < x1) && (tx1 > x0) && (ty0 < y1) && (ty1 > y0);
            float xi0 = fmaxf(tx0, x0), yi0 = fmaxf(ty0, y0);
            float xi1 = fminf(tx1, x1), yi1 = fminf(ty1, y1);
            float inter = overlap ? (xi1 - xi0) * (yi1 - yi0) : 0.f;
            float a1 = w1 * h1, a2 = w2 * h2;
            float uni = a1 + a2 - inter;
            t[7] = inter / uni; t[8] = inter / a1; t[9] = inter / a2;

            float degree = atan2f(fabsf(dy), fabsf(dx)) * 57.29577951308232f;
            float bucket;
            if      (degree >  22.5f && degree <=  67.5f) bucket = 1.f;
            else if (degree >  67.5f && degree <= 112.5f) bucket = 2.f;
            else if (degree > 112.5f && degree <= 157.5f) bucket = 3.f;
            else if (degree > 157.5f && degree <= 202.5f) bucket = 4.f;
            else if (degree > 202.5f && degree <= 247.5f) bucket = 5.f;
            else if (degree > 247.5f && degree <= 292.5f) bucket = 6.f;
            else if (degree > 292.5f && degree <= 337.5f) bucket = 7.f;
            else bucket = 8.f;
            t[10] = bucket;

            // closed-form LN stats: S1 = t.ws + sum_b ; S2 = t'Gt + 2 t.Wb + sum_b2
            const float* G  = st;
            const float* ws = st + 121;
            const float* Wb = st + 132;
            float S1 = st[143];
            float S2 = st[144];
            #pragma unroll
            for (int i = 0; i < F; i++) {
                S1 += t[i] * ws[i];
                S2 += 2.f * t[i] * Wb[i];
                float gi = 0.f;
                #pragma unroll
                for (int j = 0; j < F; j++) gi += G[i * 11 + j] * t[j];
                S2 += t[i] * gi;
            }
            float mean = S1 * (1.f / (float)H);
            float var  = S2 * (1.f / (float)H) - mean * mean;
            float inv  = rsqrtf(var + LN_EPS);

            float2* fp = (float2*)fst[tid];
            #pragma unroll
            for (int i = 0; i < F; i++) {
                float u = t[i] * inv;
                fp[i] = make_float2(u, u);
            }
            fp[11] = make_float2(inv, inv);
            float p = -mean * inv;
            fp[12] = make_float2(p, p);
        }
    }
    __syncthreads();   // fst ready; st no longer needed (obuf[0] reusable)

    bool interior = (r0blk + RPB <= N);

    // ---- chunk loop: compute into smem, bulk-store to global ----
    #pragma unroll 1
    for (int c = 0; c < NCHUNK; ++c) {
        int cr0 = r0blk + c * CHUNK;
        if (cr0 >= N) break;
        float* buf = obuf[c % NBUF];

        if (c >= NBUF) {
            if (tid == 0)
                asm volatile("cp.async.bulk.wait_group %0;" :: "n"(NBUF - 1) : "memory");
            __syncthreads();
        }

        int nrows;
        if (interior) {
            nrows = CHUNK;
            #pragma unroll 2
            for (int i = 0; i < CHUNK; ++i)
                compute_row(fst[c * CHUNK + i], C, buf + i * H, h0);
        } else {
            nrows = min(CHUNK, N - cr0);
            for (int i = 0; i < nrows; ++i)
                compute_row(fst[c * CHUNK + i], C, buf + i * H, h0);
        }

        asm volatile("fence.proxy.async.shared::cta;" ::: "memory");
        __syncthreads();

        if (tid == 0) {
            uint32_t saddr = smem_u32(buf);
            const void* gptr = (const void*)(out + (size_t)cr0 * H);
            uint32_t bytes = (uint32_t)nrows * ROWBYTES;
            asm volatile(
                "cp.async.bulk.global.shared::cta.bulk_group [%0], [%1], %2;"
                :: "l"(gptr), "r"(saddr), "r"(bytes) : "memory");
            asm volatile("cp.async.bulk.commit_group;" ::: "memory");
        }
    }

    if (tid == 0)
        asm volatile("cp.async.bulk.wait_group 0;" ::: "memory");
}

// ---------------------------------------------------------------------------
extern "C" void kernel_launch(void* const* d_in, const int* in_sizes, int n_in,
                              void* d_out, int out_size) {
    if (n_in < 6) return;
    const float* target = (const float*)d_in[0];
    const float* boxes  = (const float*)d_in[1];
    const float* W      = (const float*)d_in[2];
    const float* b      = (const float*)d_in[3];
    const float* gamma  = (const float*)d_in[4];
    const float* beta   = (const float*)d_in[5];
    float* out = (float*)d_out;

    int N = in_sizes[1] / 4;

    stats_kernel<<<145, 256>>>(W, b);
    fused_kernel<<<(N + RPB - 1) / RPB, TPB>>>(target, boxes, W, b, gamma, beta, out, N);
}

// round 14
// speedup vs baseline: 1.0302x; 1.0302x over previous
#include <cuda_runtime.h>
#include <cstdint>

#define LN_EPS 1e-5f
#define H 768
#define F 11
#define RPB 64            // rows per tile
#define TPB 128           // 128 threads x 6 cols = 768
#define COLS 6
#define NPK 3             // f32x2 packs per thread
#define CHUNK 4           // rows per bulk-store chunk (12KB)
#define NBUF 4            // tile buffers (rolling pipeline)
#define NCHUNK (RPB / CHUNK)
#define ROWBYTES (H * 4)  // 3072
#define FSTRIDE 28        // floats per fst row (13 dup pairs + 2 pad)
#define GRID 444          // 148 SMs x 3 resident CTAs

// [0..120] G[i*11+j], [121..131] ws, [132..142] Wb, [143] sum_b, [144] sum_b2
__device__ float g_stats[145];

typedef unsigned long long ull;

__device__ __forceinline__ ull fma2(ull a, ull b, ull c) {
    ull d; asm("fma.rn.f32x2 %0, %1, %2, %3;" : "=l"(d) : "l"(a), "l"(b), "l"(c)); return d;
}
__device__ __forceinline__ void unpk(ull v, float& lo, float& hi) {
    asm("mov.b64 {%0, %1}, %2;" : "=f"(lo), "=f"(hi) : "l"(v));
}
__device__ __forceinline__ ull pk2(float lo, float hi) {
    ull d; asm("mov.b64 %0, {%1, %2};" : "=l"(d) : "f"(lo), "f"(hi)); return d;
}
__device__ __forceinline__ uint32_t smem_u32(const void* p) {
    uint32_t a;
    asm("{ .reg .u64 t; cvta.to.shared.u64 t, %1; cvt.u32.u64 %0, t; }" : "=r"(a) : "l"(p));
    return a;
}

// ---------------------------------------------------------------------------
// Kernel A: weight statistics (145 tiny reductions over H=768)
// ---------------------------------------------------------------------------
__global__ void stats_kernel(const float* __restrict__ W, const float* __restrict__ b) {
    __shared__ float wsum[8];
    int blk = blockIdx.x, tid = threadIdx.x;
    float local = 0.f;
    if (blk < 121) {
        int i = blk / 11, j = blk % 11;
        for (int h = tid; h < H; h += 256) local += W[i * H + h] * W[j * H + h];
    } else if (blk < 132) {
        int f = blk - 121;
        for (int h = tid; h < H; h += 256) local += W[f * H + h];
    } else if (blk < 143) {
        int f = blk - 132;
        for (int h = tid; h < H; h += 256) local += W[f * H + h] * b[h];
    } else if (blk == 143) {
        for (int h = tid; h < H; h += 256) local += b[h];
    } else {
        for (int h = tid; h < H; h += 256) local += b[h] * b[h];
    }
    #pragma unroll
    for (int o = 16; o; o >>= 1) local += __shfl_xor_sync(0xffffffffu, local, o);
    if ((tid & 31) == 0) wsum[tid >> 5] = local;
    __syncthreads();
    if (tid == 0) {
        float s = 0.f;
        #pragma unroll
        for (int w = 0; w < 8; w++) s += wsum[w];
        g_stats[blk] = s;
    }
}

// ---------------------------------------------------------------------------
// Row compute core: one row's GEMV+LN+ReLU into smem tile (6 cols/thread)
// ---------------------------------------------------------------------------
struct ColCtx {
    ull gp[NPK], ep[NPK], bg[NPK];
    ull wg[F][NPK];
};

__device__ __forceinline__ void compute_row(const float* __restrict__ fsrow,
                                            const ColCtx& C, float* __restrict__ dst,
                                            int h0) {
    const ulonglong2* fq = (const ulonglong2*)fsrow;
    ulonglong2 q0 = fq[0], q1 = fq[1], q2 = fq[2];
    ulonglong2 q3 = fq[3], q4 = fq[4], q5 = fq[5];
    ull last = *(const ull*)(fsrow + 24);
    ull u[F] = {q0.x, q0.y, q1.x, q1.y, q2.x, q2.y,
                q3.x, q3.y, q4.x, q4.y, q5.x};
    ull s2 = q5.y;   // (inv, inv)
    ull p2 = last;   // (-mean*inv, -mean*inv)

    ull acc[NPK];
    #pragma unroll
    for (int k = 0; k < NPK; k++) acc[k] = fma2(p2, C.gp[k], C.ep[k]);
    #pragma unroll
    for (int k = 0; k < NPK; k++) acc[k] = fma2(s2, C.bg[k], acc[k]);
    #pragma unroll
    for (int f = 0; f < F; f++) {
        #pragma unroll
        for (int k = 0; k < NPK; k++) acc[k] = fma2(u[f], C.wg[f][k], acc[k]);
    }

    float v0, v1, v2, v3, v4, v5;
    unpk(acc[0], v0, v1); unpk(acc[1], v2, v3); unpk(acc[2], v4, v5);
    float2* op = (float2*)(dst + h0);
    op[0] = make_float2(fmaxf(v0, 0.f), fmaxf(v1, 0.f));
    op[1] = make_float2(fmaxf(v2, 0.f), fmaxf(v3, 0.f));
    op[2] = make_float2(fmaxf(v4, 0.f), fmaxf(v5, 0.f));
}

// ---------------------------------------------------------------------------
// Kernel B: PERSISTENT fused kernel. 444 CTAs grid-stride over row tiles;
// W regs loaded once per CTA; TMA bulk-store pipeline rolls across tiles.
// ---------------------------------------------------------------------------
__global__ void __launch_bounds__(TPB, 3)
fused_kernel(const float* __restrict__ target, const float* __restrict__ boxes,
             const float* __restrict__ W, const float* __restrict__ b,
             const float* __restrict__ gamma, const float* __restrict__ beta,
             float* __restrict__ out, int N) {
    __shared__ __align__(128) float obuf[NBUF][CHUNK * H];   // 4 x 12KB
    __shared__ __align__(16)  float fst[RPB][FSTRIDE];       // 7KB
    __shared__ float st[148];                                 // weight stats

    int tid = threadIdx.x;
    int h0 = tid * COLS;

    for (int i = tid; i < 145; i += TPB) st[i] = g_stats[i];

    // resident slices (packed pairs): wg = W*gamma, bg = b*gamma, gp, ep
    ColCtx C;
    float g6[COLS];
    {
        const float2* g2 = (const float2*)(gamma + h0);
        const float2* e2 = (const float2*)(beta + h0);
        const float2* b2 = (const float2*)(b + h0);
        #pragma unroll
        for (int k = 0; k < NPK; k++) {
            float2 g = g2[k], e = e2[k], bb = b2[k];
            g6[2*k] = g.x; g6[2*k+1] = g.y;
            C.gp[k] = pk2(g.x, g.y);
            C.ep[k] = pk2(e.x, e.y);
            C.bg[k] = pk2(bb.x * g.x, bb.y * g.y);
        }
    }
    #pragma unroll
    for (int f = 0; f < F; f++) {
        const float2* w2 = (const float2*)(W + f * H + h0);
        #pragma unroll
        for (int k = 0; k < NPK; k++) {
            float2 wv = w2[k];
            C.wg[f][k] = pk2(wv.x * g6[2*k], wv.y * g6[2*k+1]);
        }
    }

    int ntiles = (N + RPB - 1) / RPB;
    int cc = 0;   // global chunk counter (rolls across tiles)

    float tx0 = target[0], ty0 = target[1], tx1 = target[2], ty1 = target[3];
    __syncthreads();   // st[] ready

    for (int tile = blockIdx.x; tile < ntiles; tile += GRID) {
        int r0blk = tile * RPB;

        // ---- feats phase: one row per thread (tid < 64) ----
        // Safe to overwrite fst: previous tile's last chunk ended with a
        // __syncthreads after all fst reads completed.
        if (tid < RPB) {
            int row = r0blk + tid;
            if (row < N) {
                float4 bx = ((const float4*)boxes)[row];
                float x0 = bx.x, y0 = bx.y, x1 = bx.z, y1 = bx.w;

                float w1 = tx1 - tx0, h1 = ty1 - ty0;
                float w2 = x1 - x0,   h2 = y1 - y0;

                float t[F];
                t[0] = w1; t[1] = h1; t[2] = w2; t[3] = h2;
                t[4] = fabsf(w1 - w2); t[5] = fabsf(h1 - h2);

                float c1x = (tx0 + tx1) * 0.5f, c1y = (ty0 + ty1) * 0.5f;
                float c2x = (x0 + x1) * 0.5f,   c2y = (y0 + y1) * 0.5f;
                float dx = c2x - c1x, dy = c2y - c1y;
                t[6] = sqrtf(dx * dx + dy * dy);

                bool overlap = (tx0 < x1) && (tx1 > x0) && (ty0 < y1) && (ty1 > y0);
                float xi0 = fmaxf(tx0, x0), yi0 = fmaxf(ty0, y0);
                float xi1 = fminf(tx1, x1), yi1 = fminf(ty1, y1);
                float inter = overlap ? (xi1 - xi0) * (yi1 - yi0) : 0.f;
                float a1 = w1 * h1, a2 = w2 * h2;
                float uni = a1 + a2 - inter;
                t[7] = inter / uni; t[8] = inter / a1; t[9] = inter / a2;

                float degree = atan2f(fabsf(dy), fabsf(dx)) * 57.29577951308232f;
                float bucket;
                if      (degree >  22.5f && degree <=  67.5f) bucket = 1.f;
                else if (degree >  67.5f && degree <= 112.5f) bucket = 2.f;
                else if (degree > 112.5f && degree <= 157.5f) bucket = 3.f;
                else if (degree > 157.5f && degree <= 202.5f) bucket = 4.f;
                else if (degree > 202.5f && degree <= 247.5f) bucket = 5.f;
                else if (degree > 247.5f && degree <= 292.5f) bucket = 6.f;
                else if (degree > 292.5f && degree <= 337.5f) bucket = 7.f;
                else bucket = 8.f;
                t[10] = bucket;

                // closed-form LN stats
                const float* G  = st;
                const float* ws = st + 121;
                const float* Wb = st + 132;
                float S1 = st[143];
                float S2 = st[144];
                #pragma unroll
                for (int i = 0; i < F; i++) {
                    S1 += t[i] * ws[i];
                    S2 += 2.f * t[i] * Wb[i];
                    float gi = 0.f;
                    #pragma unroll
                    for (int j = 0; j < F; j++) gi += G[i * 11 + j] * t[j];
                    S2 += t[i] * gi;
                }
                float mean = S1 * (1.f / (float)H);
                float var  = S2 * (1.f / (float)H) - mean * mean;
                float inv  = rsqrtf(var + LN_EPS);

                float2* fp = (float2*)fst[tid];
                #pragma unroll
                for (int i = 0; i < F; i++) {
                    float u = t[i] * inv;
                    fp[i] = make_float2(u, u);
                }
                fp[11] = make_float2(inv, inv);
                float p = -mean * inv;
                fp[12] = make_float2(p, p);
            }
        }
        __syncthreads();   // fst ready

        bool interior = (r0blk + RPB <= N);

        // ---- chunk loop: rolling TMA pipeline across tiles ----
        #pragma unroll 1
        for (int c = 0; c < NCHUNK; ++c) {
            int cr0 = r0blk + c * CHUNK;
            if (cr0 >= N) break;
            float* buf = obuf[cc % NBUF];

            if (cc >= NBUF) {
                if (tid == 0)
                    asm volatile("cp.async.bulk.wait_group %0;" :: "n"(NBUF - 1) : "memory");
                __syncthreads();
            }

            int nrows;
            if (interior) {
                nrows = CHUNK;
                #pragma unroll 2
                for (int i = 0; i < CHUNK; ++i)
                    compute_row(fst[c * CHUNK + i], C, buf + i * H, h0);
            } else {
                nrows = min(CHUNK, N - cr0);
                for (int i = 0; i < nrows; ++i)
                    compute_row(fst[c * CHUNK + i], C, buf + i * H, h0);
            }

            asm volatile("fence.proxy.async.shared::cta;" ::: "memory");
            __syncthreads();

            if (tid == 0) {
                uint32_t saddr = smem_u32(buf);
                const void* gptr = (const void*)(out + (size_t)cr0 * H);
                uint32_t bytes = (uint32_t)nrows * ROWBYTES;
                asm volatile(
                    "cp.async.bulk.global.shared::cta.bulk_group [%0], [%1], %2;"
                    :: "l"(gptr), "r"(saddr), "r"(bytes) : "memory");
                asm volatile("cp.async.bulk.commit_group;" ::: "memory");
            }
            ++cc;
        }
    }

    if (tid == 0)
        asm volatile("cp.async.bulk.wait_group 0;" ::: "memory");
}

// ---------------------------------------------------------------------------
extern "C" void kernel_launch(void* const* d_in, const int* in_sizes, int n_in,
                              void* d_out, int out_size) {
    if (n_in < 6) return;
    const float* target = (const float*)d_in[0];
    const float* boxes  = (const float*)d_in[1];
    const float* W      = (const float*)d_in[2];
    const float* b      = (const float*)d_in[3];
    const float* gamma  = (const float*)d_in[4];
    const float* beta   = (const float*)d_in[5];
    float* out = (float*)d_out;

    int N = in_sizes[1] / 4;

    stats_kernel<<<145, 256>>>(W, b);
    fused_kernel<<<GRID, TPB>>>(target, boxes, W, b, gamma, beta, out, N);
}

// round 15
// speedup vs baseline: 1.0634x; 1.0322x over previous
#include <cuda_runtime.h>
#include <cstdint>

#define LN_EPS 1e-5f
#define H 768
#define F 11
#define RPB 64            // rows per tile
#define TPB 128           // 128 threads x 6 cols = 768
#define COLS 6
#define NPK 3             // f32x2 packs per thread
#define CHUNK 4           // rows per bulk-store chunk (12KB)
#define NBUF 4            // tile buffers (rolling pipeline)
#define NCHUNK (RPB / CHUNK)
#define ROWBYTES (H * 4)  // 3072
#define FSTRIDE 28        // floats per fst row (13 dup pairs + 2 pad)
#define GRID 444          // 148 SMs x 3 resident CTAs

// [0..120] G[i*11+j], [121..131] ws, [132..142] Wb, [143] sum_b, [144] sum_b2
__device__ float g_stats[145];

typedef unsigned long long ull;

__device__ __forceinline__ ull fma2(ull a, ull b, ull c) {
    ull d; asm("fma.rn.f32x2 %0, %1, %2, %3;" : "=l"(d) : "l"(a), "l"(b), "l"(c)); return d;
}
__device__ __forceinline__ void unpk(ull v, float& lo, float& hi) {
    asm("mov.b64 {%0, %1}, %2;" : "=f"(lo), "=f"(hi) : "l"(v));
}
__device__ __forceinline__ ull pk2(float lo, float hi) {
    ull d; asm("mov.b64 %0, {%1, %2};" : "=l"(d) : "f"(lo), "f"(hi)); return d;
}
__device__ __forceinline__ uint32_t smem_u32(const void* p) {
    uint32_t a;
    asm("{ .reg .u64 t; cvta.to.shared.u64 t, %1; cvt.u32.u64 %0, t; }" : "=r"(a) : "l"(p));
    return a;
}

// ---------------------------------------------------------------------------
// Kernel A: weight statistics (145 tiny reductions over H=768)
// ---------------------------------------------------------------------------
__global__ void stats_kernel(const float* __restrict__ W, const float* __restrict__ b) {
    __shared__ float wsum[8];
    int blk = blockIdx.x, tid = threadIdx.x;
    float local = 0.f;
    if (blk < 121) {
        int i = blk / 11, j = blk % 11;
        for (int h = tid; h < H; h += 256) local += W[i * H + h] * W[j * H + h];
    } else if (blk < 132) {
        int f = blk - 121;
        for (int h = tid; h < H; h += 256) local += W[f * H + h];
    } else if (blk < 143) {
        int f = blk - 132;
        for (int h = tid; h < H; h += 256) local += W[f * H + h] * b[h];
    } else if (blk == 143) {
        for (int h = tid; h < H; h += 256) local += b[h];
    } else {
        for (int h = tid; h < H; h += 256) local += b[h] * b[h];
    }
    #pragma unroll
    for (int o = 16; o; o >>= 1) local += __shfl_xor_sync(0xffffffffu, local, o);
    if ((tid & 31) == 0) wsum[tid >> 5] = local;
    __syncthreads();
    if (tid == 0) {
        float s = 0.f;
        #pragma unroll
        for (int w = 0; w < 8; w++) s += wsum[w];
        g_stats[blk] = s;
    }
#if defined(__CUDA_ARCH__) && __CUDA_ARCH__ >= 900
    cudaTriggerProgrammaticLaunchCompletion();
#endif
}

// ---------------------------------------------------------------------------
// Row compute core: one row's GEMV+LN+ReLU into smem tile (6 cols/thread)
// ---------------------------------------------------------------------------
struct ColCtx {
    ull gp[NPK], ep[NPK], bg[NPK];
    ull wg[F][NPK];
};

__device__ __forceinline__ void compute_row(const float* __restrict__ fsrow,
                                            const ColCtx& C, float* __restrict__ dst,
                                            int h0) {
    const ulonglong2* fq = (const ulonglong2*)fsrow;
    ulonglong2 q0 = fq[0], q1 = fq[1], q2 = fq[2];
    ulonglong2 q3 = fq[3], q4 = fq[4], q5 = fq[5];
    ull last = *(const ull*)(fsrow + 24);
    ull u[F] = {q0.x, q0.y, q1.x, q1.y, q2.x, q2.y,
                q3.x, q3.y, q4.x, q4.y, q5.x};
    ull s2 = q5.y;   // (inv, inv)
    ull p2 = last;   // (-mean*inv, -mean*inv)

    ull acc[NPK];
    #pragma unroll
    for (int k = 0; k < NPK; k++) acc[k] = fma2(p2, C.gp[k], C.ep[k]);
    #pragma unroll
    for (int k = 0; k < NPK; k++) acc[k] = fma2(s2, C.bg[k], acc[k]);
    #pragma unroll
    for (int f = 0; f < F; f++) {
        #pragma unroll
        for (int k = 0; k < NPK; k++) acc[k] = fma2(u[f], C.wg[f][k], acc[k]);
    }

    float v0, v1, v2, v3, v4, v5;
    unpk(acc[0], v0, v1); unpk(acc[1], v2, v3); unpk(acc[2], v4, v5);
    float2* op = (float2*)(dst + h0);
    op[0] = make_float2(fmaxf(v0, 0.f), fmaxf(v1, 0.f));
    op[1] = make_float2(fmaxf(v2, 0.f), fmaxf(v3, 0.f));
    op[2] = make_float2(fmaxf(v4, 0.f), fmaxf(v5, 0.f));
}

// ---------------------------------------------------------------------------
// Kernel B: PERSISTENT fused kernel with PDL. W prologue overlaps the stats
// kernel; grid-dependency sync gates only the g_stats read.
// ---------------------------------------------------------------------------
__global__ void __launch_bounds__(TPB, 3)
fused_kernel(const float* __restrict__ target, const float* __restrict__ boxes,
             const float* __restrict__ W, const float* __restrict__ b,
             const float* __restrict__ gamma, const float* __restrict__ beta,
             float* __restrict__ out, int N) {
    __shared__ __align__(128) float obuf[NBUF][CHUNK * H];   // 4 x 12KB
    __shared__ __align__(16)  float fst[RPB][FSTRIDE];       // 7KB
    __shared__ float st[148];                                 // weight stats

    int tid = threadIdx.x;
    int h0 = tid * COLS;

    // ---- prologue: param-only loads (runs concurrently with stats_kernel) ----
    ColCtx C;
    float g6[COLS];
    {
        const float2* g2 = (const float2*)(gamma + h0);
        const float2* e2 = (const float2*)(beta + h0);
        const float2* b2 = (const float2*)(b + h0);
        #pragma unroll
        for (int k = 0; k < NPK; k++) {
            float2 g = g2[k], e = e2[k], bb = b2[k];
            g6[2*k] = g.x; g6[2*k+1] = g.y;
            C.gp[k] = pk2(g.x, g.y);
            C.ep[k] = pk2(e.x, e.y);
            C.bg[k] = pk2(bb.x * g.x, bb.y * g.y);
        }
    }
    #pragma unroll
    for (int f = 0; f < F; f++) {
        const float2* w2 = (const float2*)(W + f * H + h0);
        #pragma unroll
        for (int k = 0; k < NPK; k++) {
            float2 wv = w2[k];
            C.wg[f][k] = pk2(wv.x * g6[2*k], wv.y * g6[2*k+1]);
        }
    }
    float tx0 = target[0], ty0 = target[1], tx1 = target[2], ty1 = target[3];

    // ---- wait for stats_kernel results, then stage them ----
#if defined(__CUDA_ARCH__) && __CUDA_ARCH__ >= 900
    cudaGridDependencySynchronize();
#endif
    for (int i = tid; i < 145; i += TPB) st[i] = g_stats[i];

    int ntiles = (N + RPB - 1) / RPB;
    int cc = 0;   // global chunk counter (rolls across tiles)
    __syncthreads();   // st[] ready

    for (int tile = blockIdx.x; tile < ntiles; tile += GRID) {
        int r0blk = tile * RPB;

        // ---- feats phase: one row per thread (tid < 64) ----
        if (tid < RPB) {
            int row = r0blk + tid;
            if (row < N) {
                float4 bx = ((const float4*)boxes)[row];
                float x0 = bx.x, y0 = bx.y, x1 = bx.z, y1 = bx.w;

                float w1 = tx1 - tx0, h1 = ty1 - ty0;
                float w2 = x1 - x0,   h2 = y1 - y0;

                float t[F];
                t[0] = w1; t[1] = h1; t[2] = w2; t[3] = h2;
                t[4] = fabsf(w1 - w2); t[5] = fabsf(h1 - h2);

                float c1x = (tx0 + tx1) * 0.5f, c1y = (ty0 + ty1) * 0.5f;
                float c2x = (x0 + x1) * 0.5f,   c2y = (y0 + y1) * 0.5f;
                float dx = c2x - c1x, dy = c2y - c1y;
                t[6] = sqrtf(dx * dx + dy * dy);

                bool overlap = (tx0 < x1) && (tx1 > x0) && (ty0 < y1) && (ty1 > y0);
                float xi0 = fmaxf(tx0, x0), yi0 = fmaxf(ty0, y0);
                float xi1 = fminf(tx1, x1), yi1 = fminf(ty1, y1);
                float inter = overlap ? (xi1 - xi0) * (yi1 - yi0) : 0.f;
                float a1 = w1 * h1, a2 = w2 * h2;
                float uni = a1 + a2 - inter;
                t[7] = inter / uni; t[8] = inter / a1; t[9] = inter / a2;

                float degree = atan2f(fabsf(dy), fabsf(dx)) * 57.29577951308232f;
                float bucket;
                if      (degree >  22.5f && degree <=  67.5f) bucket = 1.f;
                else if (degree >  67.5f && degree <= 112.5f) bucket = 2.f;
                else if (degree > 112.5f && degree <= 157.5f) bucket = 3.f;
                else if (degree > 157.5f && degree <= 202.5f) bucket = 4.f;
                else if (degree > 202.5f && degree <= 247.5f) bucket = 5.f;
                else if (degree > 247.5f && degree <= 292.5f) bucket = 6.f;
                else if (degree > 292.5f && degree <= 337.5f) bucket = 7.f;
                else bucket = 8.f;
                t[10] = bucket;

                // closed-form LN stats
                const float* G  = st;
                const float* ws = st + 121;
                const float* Wb = st + 132;
                float S1 = st[143];
                float S2 = st[144];
                #pragma unroll
                for (int i = 0; i < F; i++) {
                    S1 += t[i] * ws[i];
                    S2 += 2.f * t[i] * Wb[i];
                    float gi = 0.f;
                    #pragma unroll
                    for (int j = 0; j < F; j++) gi += G[i * 11 + j] * t[j];
                    S2 += t[i] * gi;
                }
                float mean = S1 * (1.f / (float)H);
                float var  = S2 * (1.f / (float)H) - mean * mean;
                float inv  = rsqrtf(var + LN_EPS);

                float2* fp = (float2*)fst[tid];
                #pragma unroll
                for (int i = 0; i < F; i++) {
                    float u = t[i] * inv;
                    fp[i] = make_float2(u, u);
                }
                fp[11] = make_float2(inv, inv);
                float p = -mean * inv;
                fp[12] = make_float2(p, p);
            }
        }
        __syncthreads();   // fst ready

        bool interior = (r0blk + RPB <= N);

        // ---- chunk loop: rolling TMA pipeline across tiles ----
        #pragma unroll 1
        for (int c = 0; c < NCHUNK; ++c) {
            int cr0 = r0blk + c * CHUNK;
            if (cr0 >= N) break;
            float* buf = obuf[cc % NBUF];

            if (cc >= NBUF) {
                if (tid == 0)
                    asm volatile("cp.async.bulk.wait_group %0;" :: "n"(NBUF - 1) : "memory");
                __syncthreads();
            }

            int nrows;
            if (interior) {
                nrows = CHUNK;
                #pragma unroll 2
                for (int i = 0; i < CHUNK; ++i)
                    compute_row(fst[c * CHUNK + i], C, buf + i * H, h0);
            } else {
                nrows = min(CHUNK, N - cr0);
                for (int i = 0; i < nrows; ++i)
                    compute_row(fst[c * CHUNK + i], C, buf + i * H, h0);
            }

            asm volatile("fence.proxy.async.shared::cta;" ::: "memory");
            __syncthreads();

            if (tid == 0) {
                uint32_t saddr = smem_u32(buf);
                const void* gptr = (const void*)(out + (size_t)cr0 * H);
                uint32_t bytes = (uint32_t)nrows * ROWBYTES;
                asm volatile(
                    "cp.async.bulk.global.shared::cta.bulk_group [%0], [%1], %2;"
                    :: "l"(gptr), "r"(saddr), "r"(bytes) : "memory");
                asm volatile("cp.async.bulk.commit_group;" ::: "memory");
            }
            ++cc;
        }
    }

    if (tid == 0)
        asm volatile("cp.async.bulk.wait_group 0;" ::: "memory");
}

// ---------------------------------------------------------------------------
extern "C" void kernel_launch(void* const* d_in, const int* in_sizes, int n_in,
                              void* d_out, int out_size) {
    if (n_in < 6) return;
    const float* target = (const float*)d_in[0];
    const float* boxes  = (const float*)d_in[1];
    const float* W      = (const float*)d_in[2];
    const float* b      = (const float*)d_in[3];
    const float* gamma  = (const float*)d_in[4];
    const float* beta   = (const float*)d_in[5];
    float* out = (float*)d_out;

    int N = in_sizes[1] / 4;

    stats_kernel<<<145, 256>>>(W, b);

    // PDL launch: fused prologue overlaps stats_kernel; falls back to a
    // plain launch if the attribute is rejected.
    cudaLaunchConfig_t cfg = {};
    cfg.gridDim = dim3(GRID);
    cfg.blockDim = dim3(TPB);
    cfg.dynamicSmemBytes = 0;
    cfg.stream = 0;
    cudaLaunchAttribute attr[1];
    attr[0].id = cudaLaunchAttributeProgrammaticStreamSerialization;
    attr[0].val.programmaticStreamSerializationAllowed = 1;
    cfg.attrs = attr;
    cfg.numAttrs = 1;
    cudaError_t e = cudaLaunchKernelEx(&cfg, fused_kernel,
                                       target, boxes, W, b, gamma, beta, out, N);
    if (e != cudaSuccess) {
        fused_kernel<<<GRID, TPB>>>(target, boxes, W, b, gamma, beta, out, N);
    }
}